// round 15
// baseline (speedup 1.0000x reference)
#include <cuda_runtime.h>
#include <cstdint>
#include <math.h>

typedef uint32_t u32;
typedef unsigned long long u64;

__device__ __forceinline__ u64 pack2(float lo, float hi){
    u64 d; asm("mov.b64 %0, {%1, %2};" : "=l"(d) : "f"(lo), "f"(hi)); return d;
}
__device__ __forceinline__ u64 fma2(u64 a, u64 b, u64 c){
    u64 d; asm("fma.rn.f32x2 %0, %1, %2, %3;" : "=l"(d) : "l"(a), "l"(b), "l"(c)); return d;
}
__device__ __forceinline__ u64 add2(u64 a, u64 b){
    u64 d; asm("add.rn.f32x2 %0, %1, %2;" : "=l"(d) : "l"(a), "l"(b)); return d;
}
__device__ __forceinline__ float lo2(u64 v){ return __int_as_float((unsigned)(v & 0xffffffffull)); }
__device__ __forceinline__ float hi2(u64 v){ return __int_as_float((unsigned)(v >> 32)); }
__device__ __forceinline__ float tanha(float v){
    float r; asm("tanh.approx.f32 %0, %1;" : "=f"(r) : "f"(v)); return r;
}

// ---------------- scratch ----------------
// GZ[L][j] = sum_k Z[k][j] * G[L][k]   (81 x 4, fixed function of U)
__device__ float g_GZ[81 * 4];
// transposed partials: g_part[(r*3+q)*16384 + img], q in {Q, S, S2}
__device__ float g_part[42 * 16384];

// ---------------- kernel 0: build GZ (3 blocks x 512, thread = (L,k)) ----------------
// G[L][k] = (1/16) sum_{ch in 2^4} sg(ch) * (ur[k][m]ur[k][n] + ui[k][m]ui[k][n])
// then 16-lane reduce over k with Z-sign per j.
__global__ __launch_bounds__(512)
void build_GZ_kernel(const float* __restrict__ U_re,
                     const float* __restrict__ U_im)
{
    __shared__ float sur[256], sui[256];
    const int tid = threadIdx.x;
    for (int i = tid; i < 256; i += 512) { sur[i] = U_re[i]; sui[i] = U_im[i]; }
    __syncthreads();

    const int e = blockIdx.x * 512 + tid;
    const int L = e >> 4, k = e & 15;
    float g = 0.f;
    if (L < 81) {
        const int t3 = L / 27, rem = L - 27 * t3;
        const int t0 = rem / 9, r9 = rem - 9 * t0;
        const int t1 = r9 / 3,  t2 = r9 - 3 * t1;
        const int tq[4] = { t0, t1, t2, t3 };

        const float* urk = sur + k * 16;
        const float* uik = sui + k * 16;
        #pragma unroll 1
        for (int ch = 0; ch < 16; ch++) {
            int m = 0, n = 0; float sg = 1.f;
            #pragma unroll
            for (int q = 0; q < 4; q++) {
                int o = (ch >> q) & 1;
                int tv = tq[q];
                int bm, bn;
                if (tv == 2) { bm = o; bn = 1 - o; }
                else         { bm = o; bn = o; if (tv == 1 && o) sg = -sg; }
                m |= bm << (3 - q);
                n |= bn << (3 - q);
            }
            g = fmaf(sg, fmaf(urk[m], urk[n], uik[m] * uik[n]), g);
        }
        g *= (1.f / 16.f);
    }

    // 4 sign-weighted 16-lane reductions (j = 0..3; sign = bit (3-j) of k)
    const unsigned msk = 0xffffffffu;
    #pragma unroll
    for (int j = 0; j < 4; j++) {
        float v = ((k >> (3 - j)) & 1) ? -g : g;
        v += __shfl_down_sync(msk, v, 8, 16);
        v += __shfl_down_sync(msk, v, 4, 16);
        v += __shfl_down_sync(msk, v, 2, 16);
        v += __shfl_down_sync(msk, v, 1, 16);
        if (k == 0 && L < 81) g_GZ[L * 4 + j] = v;
    }
}

// ---------------- kernel 1: per-patch trig-poly eval, C built in prologue ----------------
#define PK_THREADS 128

__global__ __launch_bounds__(PK_THREADS)
void patch_kernel(const float* __restrict__ x,
                  const float* __restrict__ w_cls, int bsz)
{
    __shared__ __align__(16) u64 sC[7 * 90];        // 5040 B
    __shared__ float sGZ[81 * 4];                   // 1296 B
    __shared__ float sW[56];                        // w_cls for this row's 14 patches
    __shared__ float spx[PK_THREADS * 58];          // 29696 B

    const int r    = blockIdx.x;                    // 0..13
    const int tid  = threadIdx.x;
    const int img0 = blockIdx.y * PK_THREADS;
    const int img  = img0 + tid;
    const int nimg = min(PK_THREADS, bsz - img0);

    // stage GZ + w_cls slice, then derive packed C in-block (no global round-trip)
    for (int i = tid; i < 324; i += PK_THREADS) sGZ[i] = g_GZ[i];
    if (tid < 56) sW[tid] = w_cls[1 + 56 * r + tid];

    const float* xbase = x + (size_t)img0 * 784 + r * 56;
    for (int idx = tid; idx < PK_THREADS * 56; idx += PK_THREADS) {
        int i = idx / 56, f = idx - i * 56;
        spx[i * 58 + f] = (i < nimg) ? xbase[(size_t)i * 784 + f] : 0.f;
    }
    __syncthreads();

    for (int i = tid; i < 7 * 81; i += PK_THREADS) {
        int j = i / 81, L = i - 81 * j;
        int t3 = L / 27, rem = L - 27 * t3;
        int t0 = rem / 9, r9 = rem - 9 * t0;
        int t1 = r9 / 3,  t2 = r9 - 3 * t1;
        const float* gz = sGZ + L * 4;
        const float* wa = sW + 8 * j;       // patch 2j
        const float* wb = wa + 4;           // patch 2j+1
        float accA = fmaf(wa[3], gz[3], fmaf(wa[2], gz[2], fmaf(wa[1], gz[1], wa[0] * gz[0])));
        float accB = fmaf(wb[3], gz[3], fmaf(wb[2], gz[2], fmaf(wb[1], gz[1], wb[0] * gz[0])));
        sC[j * 90 + (t0 * 3 + t1) * 10 + t3 * 3 + t2] = pack2(accA, accB);
    }
    __syncthreads();

    const float* my = spx + tid * 58;
    const u64 ONEv = pack2(1.f, 1.f);

    u64 sQ = 0ull;
    float sp = 0.f, sqs = 0.f;

    #pragma unroll 1
    for (int j = 0; j < 7; j++) {
        float2 a01 = *reinterpret_cast<const float2*>(my + 4 * j);
        float2 b01 = *reinterpret_cast<const float2*>(my + 4 * j + 2);
        float2 a23 = *reinterpret_cast<const float2*>(my + 28 + 4 * j);
        float2 b23 = *reinterpret_cast<const float2*>(my + 30 + 4 * j);

        sp  += (a01.x + a01.y + b01.x + b01.y) + (a23.x + a23.y + b23.x + b23.y);
        sqs += fmaf(a01.x,a01.x, fmaf(a01.y,a01.y, fmaf(b01.x,b01.x, b01.y*b01.y)))
             + fmaf(a23.x,a23.x, fmaf(a23.y,a23.y, fmaf(b23.x,b23.x, b23.y*b23.y)));

        float ca0,sa0,ca1,sa1,ca2,sa2,ca3,sa3;
        float cb0,sb0,cb1,sb1,cb2,sb2,cb3,sb3;
        __sincosf(a01.x, &sa0, &ca0);  __sincosf(a01.y, &sa1, &ca1);
        __sincosf(a23.x, &sa2, &ca2);  __sincosf(a23.y, &sa3, &ca3);
        __sincosf(b01.x, &sb0, &cb0);  __sincosf(b01.y, &sb1, &cb1);
        __sincosf(b23.x, &sb2, &cb2);  __sincosf(b23.y, &sb3, &cb3);

        u64 Fc0 = pack2(ca0, cb0), Fs0 = pack2(sa0, sb0);
        u64 Fc1 = pack2(ca1, cb1), Fs1 = pack2(sa1, sb1);
        u64 Fc2 = pack2(ca2, cb2), Fs2 = pack2(sa2, sb2);
        u64 Fc3 = pack2(ca3, cb3), Fs3 = pack2(sa3, sb3);

        const u64* Cj = sC + j * 90;
        u64 h0 = 0ull, h1 = 0ull, h2 = 0ull;

        #pragma unroll
        for (int i01 = 0; i01 < 9; i01++) {
            const u64* base = Cj + i01 * 10;
            ulonglong2 q01 = *reinterpret_cast<const ulonglong2*>(base + 0);
            ulonglong2 q23 = *reinterpret_cast<const ulonglong2*>(base + 2);
            ulonglong2 q45 = *reinterpret_cast<const ulonglong2*>(base + 4);
            ulonglong2 q67 = *reinterpret_cast<const ulonglong2*>(base + 6);
            u64 q8 = base[8];
            u64 av0 = fma2(q67.x, Fs3, fma2(q23.y, Fc3, q01.x));
            u64 av1 = fma2(q67.y, Fs3, fma2(q45.x, Fc3, q01.y));
            u64 av2 = fma2(q8,    Fs3, fma2(q45.y, Fc3, q23.x));
            u64 g   = fma2(av2, Fs2, fma2(av1, Fc2, av0));
            const int t1v = i01 % 3;
            u64 w = (t1v == 0) ? ONEv : ((t1v == 1) ? Fc1 : Fs1);
            if (i01 < 3)      h0 = fma2(g, w, h0);
            else if (i01 < 6) h1 = fma2(g, w, h1);
            else              h2 = fma2(g, w, h2);
        }
        sQ = add2(sQ, fma2(h2, Fs0, fma2(h1, Fc0, h0)));
    }

    if (img < bsz) {
        g_part[(r * 3 + 0) * 16384 + img] = lo2(sQ) + hi2(sQ);
        g_part[(r * 3 + 1) * 16384 + img] = sp;
        g_part[(r * 3 + 2) * 16384 + img] = sqs;
    }
}

// ---------------- kernel 2: 4-thread-per-image reduce + head + sigmoid ----------------
__global__ void head_kernel(
    const float* __restrict__ w_in,  const float* __restrict__ b_in,
    const float* __restrict__ scale_in, const float* __restrict__ shift_in,
    const float* __restrict__ Wc,    const float* __restrict__ bc,
    const float* __restrict__ scalec, const float* __restrict__ shiftc,
    const float* __restrict__ w_out, const float* __restrict__ b_out,
    const float* __restrict__ w_cls, const float* __restrict__ b_cls,
    float* __restrict__ out, int Lc, int bsz)
{
    const int t   = blockIdx.x * blockDim.x + threadIdx.x;
    const int img = t >> 2;
    const int s   = t & 3;
    const bool v  = img < bsz;

    float Q = 0.f, S = 0.f, S2 = 0.f;
    if (v) {
        #pragma unroll
        for (int u = 0; u < 4; u++) {
            int r = s + 4 * u;
            if (r < 14) {
                Q  += g_part[(r * 3 + 0) * 16384 + img];
                S  += g_part[(r * 3 + 1) * 16384 + img];
                S2 += g_part[(r * 3 + 2) * 16384 + img];
            }
        }
    }
    const unsigned m = 0xffffffffu;
    Q  += __shfl_down_sync(m, Q,  2, 4);  Q  += __shfl_down_sync(m, Q,  1, 4);
    S  += __shfl_down_sync(m, S,  2, 4);  S  += __shfl_down_sync(m, S,  1, 4);
    S2 += __shfl_down_sync(m, S2, 2, 4);  S2 += __shfl_down_sync(m, S2, 1, 4);

    if (v && s == 0) {
        float mean = S * (1.f/784.f);
        float var  = (S2 - S*S*(1.f/784.f)) * (1.f/783.f);
        float stdv = sqrtf(fmaxf(var, 0.f));
        float h0 = mean, h1 = stdv;
        float t0 = tanha(fmaf(w_in[0],h0, fmaf(w_in[1],h1, b_in[0]))) * scale_in[0] + shift_in[0];
        float t1 = tanha(fmaf(w_in[2],h0, fmaf(w_in[3],h1, b_in[1]))) * scale_in[1] + shift_in[1];
        h0 = t0; h1 = t1;
        for (int l = 0; l < Lc; l++) {
            float u0 = tanha(fmaf(Wc[l*4+0],h0, fmaf(Wc[l*4+1],h1, bc[l*2+0]))) * scalec[l*2+0] + shiftc[l*2+0];
            float u1 = tanha(fmaf(Wc[l*4+2],h0, fmaf(Wc[l*4+3],h1, bc[l*2+1]))) * scalec[l*2+1] + shiftc[l*2+1];
            h0 = u0; h1 = u1;
        }
        float cls   = fmaf(w_out[0],h0, fmaf(w_out[1],h1, b_out[0]));
        float logit = fmaf(w_cls[0], cls, b_cls[0]) + Q;
        out[img] = 1.f / (1.f + __expf(-logit));
    }
}

// ---------------- launch ----------------
extern "C" void kernel_launch(void* const* d_in, const int* in_sizes, int n_in,
                              void* d_out, int out_size)
{
    const float* x        = (const float*)d_in[0];
    const float* w_in     = (const float*)d_in[1];
    const float* b_in     = (const float*)d_in[2];
    const float* scale_in = (const float*)d_in[3];
    const float* shift_in = (const float*)d_in[4];
    const float* Wc       = (const float*)d_in[5];
    const float* bc       = (const float*)d_in[6];
    const float* scalec   = (const float*)d_in[7];
    const float* shiftc   = (const float*)d_in[8];
    const float* w_out    = (const float*)d_in[9];
    const float* b_out    = (const float*)d_in[10];
    const float* U_re     = (const float*)d_in[11];
    const float* U_im     = (const float*)d_in[12];
    const float* w_cls    = (const float*)d_in[13];
    const float* b_cls    = (const float*)d_in[14];
    float* out = (float*)d_out;

    const int bsz = in_sizes[0] / 784;
    const int Lc  = in_sizes[5] / 4;

    build_GZ_kernel<<<3, 512>>>(U_re, U_im);

    dim3 grid1(14, (bsz + PK_THREADS - 1) / PK_THREADS);
    patch_kernel<<<grid1, PK_THREADS>>>(x, w_cls, bsz);

    head_kernel<<<(bsz * 4 + 127) / 128, 128>>>(w_in, b_in, scale_in, shift_in,
                                                Wc, bc, scalec, shiftc,
                                                w_out, b_out, w_cls, b_cls,
                                                out, Lc, bsz);
}

// round 17
// speedup vs baseline: 1.2615x; 1.2615x over previous
#include <cuda_runtime.h>
#include <cstdint>
#include <math.h>

typedef uint32_t u32;
typedef unsigned long long u64;

__device__ __forceinline__ u64 pack2(float lo, float hi){
    u64 d; asm("mov.b64 %0, {%1, %2};" : "=l"(d) : "f"(lo), "f"(hi)); return d;
}
__device__ __forceinline__ u64 fma2(u64 a, u64 b, u64 c){
    u64 d; asm("fma.rn.f32x2 %0, %1, %2, %3;" : "=l"(d) : "l"(a), "l"(b), "l"(c)); return d;
}
__device__ __forceinline__ u64 add2(u64 a, u64 b){
    u64 d; asm("add.rn.f32x2 %0, %1, %2;" : "=l"(d) : "l"(a), "l"(b)); return d;
}
__device__ __forceinline__ float lo2(u64 v){ return __int_as_float((unsigned)(v & 0xffffffffull)); }
__device__ __forceinline__ float hi2(u64 v){ return __int_as_float((unsigned)(v >> 32)); }
__device__ __forceinline__ float tanha(float v){
    float r; asm("tanh.approx.f32 %0, %1;" : "=f"(r) : "f"(v)); return r;
}

// ---------------- scratch ----------------
// C[p][L]: per-patch trig-poly coefficients (p = r*14 + c, L = t3*27 + t0*9 + t1*3 + t2)
__device__ float g_C[196 * 81];
// transposed partials: g_part[(r*3+q)*16384 + img], q in {Q, S, S2}
__device__ float g_part[42 * 16384];

// ---------------- kernel 0: direct C build, one wide kernel ----------------
// thread = (p = blockIdx.x, L = threadIdx.x); grid 196 >= 148 (no small-grid throttle).
// C[p][L] = (1/16) sum_k v_k(p) * sum_{ch in 2^4} sg(ch) * (ur[k][m]ur[k][n] + ui[k][m]ui[k][n])
__global__ __launch_bounds__(96)
void build_C_kernel(const float* __restrict__ U_re,
                    const float* __restrict__ U_im,
                    const float* __restrict__ w_cls)
{
    __shared__ float sur[256], sui[256];
    const int tid = threadIdx.x;
    for (int i = tid; i < 256; i += 96) { sur[i] = U_re[i]; sui[i] = U_im[i]; }
    __syncthreads();

    const int L = tid;
    if (L >= 81) return;
    const int p = blockIdx.x;

    const int t3 = L / 27, rem = L - 27 * t3;
    const int t0 = rem / 9, r9 = rem - 9 * t0;
    const int t1 = r9 / 3,  t2 = r9 - 3 * t1;
    const int tq[4] = { t0, t1, t2, t3 };

    // derive the 16 (m, n, sign) channel patterns once (parallel across 196*81 threads)
    int mA[16], nA[16];
    float sgA[16];
    #pragma unroll 1
    for (int ch = 0; ch < 16; ch++) {
        int m = 0, n = 0; float sg = 1.f;
        #pragma unroll
        for (int q = 0; q < 4; q++) {
            int o = (ch >> q) & 1;
            int tv = tq[q];
            int bm, bn;
            if (tv == 2) { bm = o; bn = 1 - o; }
            else         { bm = o; bn = o; if (tv == 1 && o) sg = -sg; }
            m |= bm << (3 - q);
            n |= bn << (3 - q);
        }
        mA[ch] = m; nA[ch] = n; sgA[ch] = sg;
    }

    const float* wq = w_cls + 1 + 4 * p;
    const float w0 = wq[0], w1 = wq[1], w2 = wq[2], w3 = wq[3];

    float acc = 0.f;
    #pragma unroll 1
    for (int k = 0; k < 16; k++) {
        const float* urk = sur + k * 16;
        const float* uik = sui + k * 16;
        float g = 0.f;
        #pragma unroll
        for (int ch = 0; ch < 16; ch++)
            g = fmaf(sgA[ch], fmaf(urk[mA[ch]], urk[nA[ch]], uik[mA[ch]] * uik[nA[ch]]), g);
        float vk = ((k & 8) ? -w0 : w0) + ((k & 4) ? -w1 : w1)
                 + ((k & 2) ? -w2 : w2) + ((k & 1) ? -w3 : w3);
        acc = fmaf(vk, g, acc);
    }
    g_C[p * 81 + L] = acc * (1.f / 16.f);
}

// ---------------- kernel 1: per-patch trig-poly eval (R7 core, verbatim) ----------------
#define PK_THREADS 128

__global__ __launch_bounds__(PK_THREADS)
void patch_kernel(const float* __restrict__ x, int bsz)
{
    __shared__ __align__(16) u64 sC[7 * 90];        // 5040 B
    __shared__ float spx[PK_THREADS * 58];          // 29696 B

    const int r    = blockIdx.x;                    // 0..13
    const int tid  = threadIdx.x;
    const int img0 = blockIdx.y * PK_THREADS;
    const int img  = img0 + tid;
    const int nimg = min(PK_THREADS, bsz - img0);

    // pack this row's 14 patch-coefficient sets (pairs in f32x2 halves)
    for (int i = tid; i < 7 * 81; i += PK_THREADS) {
        int j = i / 81, L = i - 81 * j;
        int t3 = L / 27, rem = L - 27 * t3;
        int t0 = rem / 9, r9 = rem - 9 * t0;
        int t1 = r9 / 3,  t2 = r9 - 3 * t1;
        const float* cp = g_C + (r * 14 + 2 * j) * 81 + L;
        sC[j * 90 + (t0 * 3 + t1) * 10 + t3 * 3 + t2] = pack2(cp[0], cp[81]);
    }

    const float* xbase = x + (size_t)img0 * 784 + r * 56;
    for (int idx = tid; idx < PK_THREADS * 56; idx += PK_THREADS) {
        int i = idx / 56, f = idx - i * 56;
        spx[i * 58 + f] = (i < nimg) ? xbase[(size_t)i * 784 + f] : 0.f;
    }
    __syncthreads();

    const float* my = spx + tid * 58;
    const u64 ONEv = pack2(1.f, 1.f);

    u64 sQ = 0ull;
    float sp = 0.f, sqs = 0.f;

    #pragma unroll 1
    for (int j = 0; j < 7; j++) {
        float2 a01 = *reinterpret_cast<const float2*>(my + 4 * j);
        float2 b01 = *reinterpret_cast<const float2*>(my + 4 * j + 2);
        float2 a23 = *reinterpret_cast<const float2*>(my + 28 + 4 * j);
        float2 b23 = *reinterpret_cast<const float2*>(my + 30 + 4 * j);

        sp  += (a01.x + a01.y + b01.x + b01.y) + (a23.x + a23.y + b23.x + b23.y);
        sqs += fmaf(a01.x,a01.x, fmaf(a01.y,a01.y, fmaf(b01.x,b01.x, b01.y*b01.y)))
             + fmaf(a23.x,a23.x, fmaf(a23.y,a23.y, fmaf(b23.x,b23.x, b23.y*b23.y)));

        float ca0,sa0,ca1,sa1,ca2,sa2,ca3,sa3;
        float cb0,sb0,cb1,sb1,cb2,sb2,cb3,sb3;
        __sincosf(a01.x, &sa0, &ca0);  __sincosf(a01.y, &sa1, &ca1);
        __sincosf(a23.x, &sa2, &ca2);  __sincosf(a23.y, &sa3, &ca3);
        __sincosf(b01.x, &sb0, &cb0);  __sincosf(b01.y, &sb1, &cb1);
        __sincosf(b23.x, &sb2, &cb2);  __sincosf(b23.y, &sb3, &cb3);

        u64 Fc0 = pack2(ca0, cb0), Fs0 = pack2(sa0, sb0);
        u64 Fc1 = pack2(ca1, cb1), Fs1 = pack2(sa1, sb1);
        u64 Fc2 = pack2(ca2, cb2), Fs2 = pack2(sa2, sb2);
        u64 Fc3 = pack2(ca3, cb3), Fs3 = pack2(sa3, sb3);

        const u64* Cj = sC + j * 90;
        u64 h0 = 0ull, h1 = 0ull, h2 = 0ull;

        #pragma unroll
        for (int i01 = 0; i01 < 9; i01++) {
            const u64* base = Cj + i01 * 10;
            ulonglong2 q01 = *reinterpret_cast<const ulonglong2*>(base + 0);
            ulonglong2 q23 = *reinterpret_cast<const ulonglong2*>(base + 2);
            ulonglong2 q45 = *reinterpret_cast<const ulonglong2*>(base + 4);
            ulonglong2 q67 = *reinterpret_cast<const ulonglong2*>(base + 6);
            u64 q8 = base[8];
            u64 av0 = fma2(q67.x, Fs3, fma2(q23.y, Fc3, q01.x));
            u64 av1 = fma2(q67.y, Fs3, fma2(q45.x, Fc3, q01.y));
            u64 av2 = fma2(q8,    Fs3, fma2(q45.y, Fc3, q23.x));
            u64 g   = fma2(av2, Fs2, fma2(av1, Fc2, av0));
            const int t1v = i01 % 3;
            u64 w = (t1v == 0) ? ONEv : ((t1v == 1) ? Fc1 : Fs1);
            if (i01 < 3)      h0 = fma2(g, w, h0);
            else if (i01 < 6) h1 = fma2(g, w, h1);
            else              h2 = fma2(g, w, h2);
        }
        sQ = add2(sQ, fma2(h2, Fs0, fma2(h1, Fc0, h0)));
    }

    if (img < bsz) {
        g_part[(r * 3 + 0) * 16384 + img] = lo2(sQ) + hi2(sQ);
        g_part[(r * 3 + 1) * 16384 + img] = sp;
        g_part[(r * 3 + 2) * 16384 + img] = sqs;
    }
}

// ---------------- kernel 2: 4-thread-per-image reduce + head + sigmoid (R7) ----------------
__global__ void head_kernel(
    const float* __restrict__ w_in,  const float* __restrict__ b_in,
    const float* __restrict__ scale_in, const float* __restrict__ shift_in,
    const float* __restrict__ Wc,    const float* __restrict__ bc,
    const float* __restrict__ scalec, const float* __restrict__ shiftc,
    const float* __restrict__ w_out, const float* __restrict__ b_out,
    const float* __restrict__ w_cls, const float* __restrict__ b_cls,
    float* __restrict__ out, int Lc, int bsz)
{
    const int t   = blockIdx.x * blockDim.x + threadIdx.x;
    const int img = t >> 2;
    const int s   = t & 3;
    const bool v  = img < bsz;

    float Q = 0.f, S = 0.f, S2 = 0.f;
    if (v) {
        #pragma unroll
        for (int u = 0; u < 4; u++) {
            int r = s + 4 * u;
            if (r < 14) {
                Q  += g_part[(r * 3 + 0) * 16384 + img];
                S  += g_part[(r * 3 + 1) * 16384 + img];
                S2 += g_part[(r * 3 + 2) * 16384 + img];
            }
        }
    }
    const unsigned m = 0xffffffffu;
    Q  += __shfl_down_sync(m, Q,  2, 4);  Q  += __shfl_down_sync(m, Q,  1, 4);
    S  += __shfl_down_sync(m, S,  2, 4);  S  += __shfl_down_sync(m, S,  1, 4);
    S2 += __shfl_down_sync(m, S2, 2, 4);  S2 += __shfl_down_sync(m, S2, 1, 4);

    if (v && s == 0) {
        float mean = S * (1.f/784.f);
        float var  = (S2 - S*S*(1.f/784.f)) * (1.f/783.f);
        float stdv = sqrtf(fmaxf(var, 0.f));
        float h0 = mean, h1 = stdv;
        float t0 = tanha(fmaf(w_in[0],h0, fmaf(w_in[1],h1, b_in[0]))) * scale_in[0] + shift_in[0];
        float t1 = tanha(fmaf(w_in[2],h0, fmaf(w_in[3],h1, b_in[1]))) * scale_in[1] + shift_in[1];
        h0 = t0; h1 = t1;
        for (int l = 0; l < Lc; l++) {
            float u0 = tanha(fmaf(Wc[l*4+0],h0, fmaf(Wc[l*4+1],h1, bc[l*2+0]))) * scalec[l*2+0] + shiftc[l*2+0];
            float u1 = tanha(fmaf(Wc[l*4+2],h0, fmaf(Wc[l*4+3],h1, bc[l*2+1]))) * scalec[l*2+1] + shiftc[l*2+1];
            h0 = u0; h1 = u1;
        }
        float cls   = fmaf(w_out[0],h0, fmaf(w_out[1],h1, b_out[0]));
        float logit = fmaf(w_cls[0], cls, b_cls[0]) + Q;
        out[img] = 1.f / (1.f + __expf(-logit));
    }
}

// ---------------- launch ----------------
extern "C" void kernel_launch(void* const* d_in, const int* in_sizes, int n_in,
                              void* d_out, int out_size)
{
    const float* x        = (const float*)d_in[0];
    const float* w_in     = (const float*)d_in[1];
    const float* b_in     = (const float*)d_in[2];
    const float* scale_in = (const float*)d_in[3];
    const float* shift_in = (const float*)d_in[4];
    const float* Wc       = (const float*)d_in[5];
    const float* bc       = (const float*)d_in[6];
    const float* scalec   = (const float*)d_in[7];
    const float* shiftc   = (const float*)d_in[8];
    const float* w_out    = (const float*)d_in[9];
    const float* b_out    = (const float*)d_in[10];
    const float* U_re     = (const float*)d_in[11];
    const float* U_im     = (const float*)d_in[12];
    const float* w_cls    = (const float*)d_in[13];
    const float* b_cls    = (const float*)d_in[14];
    float* out = (float*)d_out;

    const int bsz = in_sizes[0] / 784;
    const int Lc  = in_sizes[5] / 4;

    build_C_kernel<<<196, 96>>>(U_re, U_im, w_cls);

    dim3 grid1(14, (bsz + PK_THREADS - 1) / PK_THREADS);
    patch_kernel<<<grid1, PK_THREADS>>>(x, bsz);

    head_kernel<<<(bsz * 4 + 127) / 128, 128>>>(w_in, b_in, scale_in, shift_in,
                                                Wc, bc, scalec, shiftc,
                                                w_out, b_out, w_cls, b_cls,
                                                out, Lc, bsz);
}